// round 13
// baseline (speedup 1.0000x reference)
#include <cuda_runtime.h>
#include <math.h>

// Problem constants (B=8, L=4096, D=1024, fp32)
#define BB 8
#define LL 4096
#define ND (LL - 1)        // 4095 deltas per batch
#define NI (LL - 2)        // 4094 loss terms per batch
#define TC 111             // terms per block
#define NDEL (TC + 1)      // 112 deltas per block (= 7 chunks of 16)
#define XBLK 37            // 37*111 = 4107 >= 4094
// grid = (37, 8) = 296 = 148 SMs * 2 CTAs -> ONE perfectly balanced wave
// 2 CTAs/SM -> 128 regs/thread -> 16 LDG.128 in flight per thread

// Accumulators. Zero-initialized at load; last block resets them each launch.
__device__ float g_ws;
__device__ float g_ms;
__device__ unsigned int g_ticket;

__device__ __forceinline__ float sqnorm_diff(float4 a, float4 b) {
    float dx = a.x - b.x, dy = a.y - b.y, dz = a.z - b.z, dw = a.w - b.w;
    return fmaf(dx, dx, fmaf(dy, dy, fmaf(dz, dz, dw * dw)));
}

// Fused kernel. Block (bx, b) owns terms t in [111*bx, 111*bx+111) ∩ [0, NI).
// Phase 1: stream 113 rows as 7 chunks x 16 rows (16 LDG.128.CS in flight,
//          128-reg budget at 2 CTAs/SM). Per delta: xor16+xor8 pre-reduce,
//          lanes 0..7 store to s_part[i][warp*8+lane] (112 x 64 = 28.7 KB).
// Phase 2: warp w reduces deltas i ≡ w (mod 8): 2 LDS + 5 SHFL + sqrt.
// Phase 3: warp 0 computes 111 weighted terms (4 per lane), one atomicAdd
//          pair per block; ticketed last block publishes out and resets.
//
// rtp dtype hedge: buffer may be int64 or int32. Read as 16 int32 words;
// little-endian int64 values < 4096 => all odd words zero => take even words.
__global__ __launch_bounds__(256, 2) void fused_kernel(const float* __restrict__ states,
                                                       const float* __restrict__ reasoning_mask,
                                                       const int* __restrict__ rtp_raw,
                                                       float* __restrict__ out) {
    const int b   = blockIdx.y;
    const int t0  = blockIdx.x * TC;
    const int tid = threadIdx.x;
    const int warp = tid >> 5;
    const int lane = tid & 31;
    const unsigned int nblocks = gridDim.x * gridDim.y;

    const float4* __restrict__ base =
        reinterpret_cast<const float4*>(states + (size_t)b * LL * (size_t)1024);

    __shared__ float s_part[NDEL][64];   // 8 group-sums per warp per delta
    __shared__ float delta_sm[NDEL];

    const int sp_col = warp * 8 + lane;  // valid when lane < 8
    const bool store_ok = (lane < 8);

    // ---- Phase 1: 7 chunks x 16 rows; deltas 0..111 ----
    if (t0 + NDEL <= LL - 1) {
        // Clean path (bx < 36): rows t0 .. t0+112 all in range.
        float4 prev = __ldcs(base + (size_t)t0 * 256 + tid);
        #pragma unroll
        for (int ch = 0; ch < 7; ch++) {
            const size_t r = (size_t)(t0 + 16 * ch + 1) * 256 + tid;
            float4 c[16];
            #pragma unroll
            for (int j = 0; j < 16; j++) c[j] = __ldcs(base + r + 256 * j);

            float s[16];
            s[0] = sqnorm_diff(c[0], prev);
            #pragma unroll
            for (int j = 1; j < 16; j++) s[j] = sqnorm_diff(c[j], c[j - 1]);

            #pragma unroll
            for (int j = 0; j < 16; j++) {
                float v = s[j] + __shfl_xor_sync(0xffffffffu, s[j], 16);
                v += __shfl_xor_sync(0xffffffffu, v, 8);
                if (store_ok) s_part[16 * ch + j][sp_col] = v;
            }
            prev = c[15];
        }
    } else {
        // Guarded path (last x-block only): clamp rows; clamped deltas are 0
        // (diff of identical rows) and their terms are masked in phase 3.
        float4 prev = __ldcs(base + (size_t)t0 * 256 + tid);
        #pragma unroll
        for (int ch = 0; ch < 7; ch++) {
            float4 c[16];
            #pragma unroll
            for (int j = 0; j < 16; j++) {
                int row = t0 + 16 * ch + 1 + j;
                if (row > LL - 1) row = LL - 1;
                c[j] = __ldcs(base + (size_t)row * 256 + tid);
            }
            float s[16];
            s[0] = sqnorm_diff(c[0], prev);
            #pragma unroll
            for (int j = 1; j < 16; j++) s[j] = sqnorm_diff(c[j], c[j - 1]);

            #pragma unroll
            for (int j = 0; j < 16; j++) {
                float v = s[j] + __shfl_xor_sync(0xffffffffu, s[j], 16);
                v += __shfl_xor_sync(0xffffffffu, v, 8);
                if (store_ok) s_part[16 * ch + j][sp_col] = v;
            }
            prev = c[15];
        }
    }

    __syncthreads();

    // ---- Phase 2: reduce 64 partials per delta. Warp w handles deltas
    //      i = w, w+8, ... < NDEL (conflict-free LDS). ----
    for (int i = warp; i < NDEL; i += 8) {
        float v = s_part[i][lane] + s_part[i][lane + 32];
        #pragma unroll
        for (int o = 16; o > 0; o >>= 1)
            v += __shfl_xor_sync(0xffffffffu, v, o);
        if (lane == 0) delta_sm[i] = sqrtf(v);
    }

    __syncthreads();

    // ---- Phase 3: loss terms, warp 0 only (111 terms, 4 per lane) ----
    if (warp == 0) {
        int odd_or = 0;
        #pragma unroll
        for (int i = 1; i < 16; i += 2) odd_or |= rtp_raw[i];
        const int rtp_b = (odd_or == 0) ? rtp_raw[2 * b] : rtp_raw[b];

        float ws = 0.0f, ms = 0.0f;
        #pragma unroll
        for (int h = 0; h < 4; h++) {
            const int li = lane + 32 * h;     // local term index
            const int t = t0 + li;
            if (li < TC && t < NI) {
                float di = fmaxf(delta_sm[li + 1] - delta_sm[li], 0.0f);
                const float m = reasoning_mask[b * LL + t + 2];
                int dist = rtp_b - t - 2;
                if (dist < 0) dist = 0;
                const float w = (dist < 5) ? (2.0f + (float)(5 - dist) * 0.5f) : 1.0f;
                ws += di * m * w;
                ms += m;
            }
        }
        #pragma unroll
        for (int o = 16; o > 0; o >>= 1) {
            ws += __shfl_xor_sync(0xffffffffu, ws, o);
            ms += __shfl_xor_sync(0xffffffffu, ms, o);
        }
        if (lane == 0) {
            atomicAdd(&g_ws, ws);
            atomicAdd(&g_ms, ms);
            __threadfence();
            const unsigned int my = atomicAdd(&g_ticket, 1u);
            if (my == nblocks - 1u) {
                __threadfence();
                const float tws = *(volatile float*)&g_ws;
                const float tms = *(volatile float*)&g_ms;
                out[0] = tws / (tms + 1e-9f);
                // reset for next graph replay (all blocks done: safe)
                g_ws = 0.0f;
                g_ms = 0.0f;
                g_ticket = 0u;
            }
        }
    }
}

extern "C" void kernel_launch(void* const* d_in, const int* in_sizes, int n_in,
                              void* d_out, int out_size) {
    const float* states = (const float*)d_in[0];
    const float* rmask  = (const float*)d_in[1];
    const int*   rtp    = (const int*)d_in[2];
    float*       out    = (float*)d_out;

    dim3 grid(XBLK, BB);   // (37, 8) = 296 blocks = 148 SMs x 2
    fused_kernel<<<grid, 256>>>(states, rmask, rtp, out);
}

// round 14
// speedup vs baseline: 1.0767x; 1.0767x over previous
#include <cuda_runtime.h>
#include <math.h>

// Problem constants (B=8, L=4096, D=1024, fp32)
#define BB 8
#define LL 4096
#define ND (LL - 1)       // 4095 deltas per batch
#define NI (LL - 2)       // 4094 loss terms per batch
#define TC 56             // terms per block
#define NDEL (TC + 1)     // 57 deltas per block (rows t0 .. t0+57)
#define XBLK 74           // blocks per batch: 74*56 = 4144 >= 4094
// grid = (74, 8) = 592 = 148 SMs * 4 CTAs -> ONE perfectly balanced wave

// Accumulators. Zero-initialized at load; last block resets them each launch.
__device__ float g_ws;
__device__ float g_ms;
__device__ unsigned int g_ticket;

__device__ __forceinline__ float sqnorm_diff(float4 a, float4 b) {
    float dx = a.x - b.x, dy = a.y - b.y, dz = a.z - b.z, dw = a.w - b.w;
    return fmaf(dx, dx, fmaf(dy, dy, fmaf(dz, dz, dw * dw)));
}

// Fused kernel (R8/R12 structure, xor16+xor8 pre-reduce -> 8-wide stores).
// Block (bx, b) owns terms t in [56*bx, 56*bx+56) ∩ [0, NI).
// Phase 1: stream 58 rows in chunks of 8 (8 LDG.128.CS in flight per thread,
//          64-reg budget at 4 CTAs/SM). Per delta: xor16+xor8 pre-reduce,
//          lanes 0..7 store into s_part[i][warp*8+lane] (57 x 64 = 14.6 KB).
// Phase 2: warp w reduces deltas i ≡ w (mod 8): 2 LDS + 5 SHFL + sqrt.
// Phase 3: warp 0 computes the 56 weighted loss terms (2 per lane), one
//          atomicAdd pair per block; ticketed last block publishes + resets.
//
// rtp dtype hedge: buffer may be int64 or int32. Read as 16 int32 words;
// little-endian int64 values < 4096 => all odd words zero => take even words.
__global__ __launch_bounds__(256, 4) void fused_kernel(const float* __restrict__ states,
                                                       const float* __restrict__ reasoning_mask,
                                                       const int* __restrict__ rtp_raw,
                                                       float* __restrict__ out) {
    const int b   = blockIdx.y;
    const int t0  = blockIdx.x * TC;
    const int tid = threadIdx.x;
    const int warp = tid >> 5;
    const int lane = tid & 31;
    const unsigned int nblocks = gridDim.x * gridDim.y;

    const float4* __restrict__ base =
        reinterpret_cast<const float4*>(states + (size_t)b * LL * (size_t)1024);

    __shared__ float s_part[NDEL][64];   // 8 group-sums per warp per delta
    __shared__ float delta_sm[NDEL];

    const int sp_col = warp * 8 + lane;  // valid when lane < 8
    const bool store_ok = (lane < 8);

    // ---- Phase 1: stream rows t0 .. t0+57, emit 57 pre-reduced partials ----
    if (t0 + NDEL <= LL - 1) {
        // Clean path: 7 chunks x 8 rows + 1 tail row. Streaming (evict-first).
        float4 prev = __ldcs(base + (size_t)t0 * 256 + tid);
        #pragma unroll
        for (int ch = 0; ch < 7; ch++) {
            const size_t r = (size_t)(t0 + 8 * ch + 1) * 256 + tid;
            float4 c[8];
            #pragma unroll
            for (int j = 0; j < 8; j++) c[j] = __ldcs(base + r + 256 * j);

            float s[8];
            s[0] = sqnorm_diff(c[0], prev);
            #pragma unroll
            for (int j = 1; j < 8; j++) s[j] = sqnorm_diff(c[j], c[j - 1]);

            #pragma unroll
            for (int j = 0; j < 8; j++) {
                float v = s[j] + __shfl_xor_sync(0xffffffffu, s[j], 16);
                v += __shfl_xor_sync(0xffffffffu, v, 8);
                if (store_ok) s_part[8 * ch + j][sp_col] = v;
            }
            prev = c[7];
        }
        float4 cl = __ldcs(base + (size_t)(t0 + NDEL) * 256 + tid);
        float vl = sqnorm_diff(cl, prev);
        vl += __shfl_xor_sync(0xffffffffu, vl, 16);
        vl += __shfl_xor_sync(0xffffffffu, vl, 8);
        if (store_ok) s_part[NDEL - 1][sp_col] = vl;
    } else {
        // Guarded path (last x-block only): clamp rows; out-of-range deltas
        // become 0 (diff of identical clamped rows) and are unused anyway.
        float4 prev = __ldcs(base + (size_t)t0 * 256 + tid);
        #pragma unroll 4
        for (int i = 0; i < NDEL; i++) {
            int row = t0 + i + 1;
            if (row > LL - 1) row = LL - 1;
            float4 cur = __ldcs(base + (size_t)row * 256 + tid);
            float v = sqnorm_diff(cur, prev);
            v += __shfl_xor_sync(0xffffffffu, v, 16);
            v += __shfl_xor_sync(0xffffffffu, v, 8);
            if (store_ok) s_part[i][sp_col] = v;
            prev = cur;
        }
    }

    __syncthreads();

    // ---- Phase 2: reduce 64 partials per delta. Warp w handles deltas
    //      i = w, w+8, ... < NDEL (conflict-free LDS). ----
    for (int i = warp; i < NDEL; i += 8) {
        float v = s_part[i][lane] + s_part[i][lane + 32];
        #pragma unroll
        for (int o = 16; o > 0; o >>= 1)
            v += __shfl_xor_sync(0xffffffffu, v, o);
        if (lane == 0) delta_sm[i] = sqrtf(v);
    }

    __syncthreads();

    // ---- Phase 3: loss terms, warp 0 only (56 terms, 2 per lane) ----
    if (warp == 0) {
        int odd_or = 0;
        #pragma unroll
        for (int i = 1; i < 16; i += 2) odd_or |= rtp_raw[i];
        const int rtp_b = (odd_or == 0) ? rtp_raw[2 * b] : rtp_raw[b];

        float ws = 0.0f, ms = 0.0f;
        #pragma unroll
        for (int h = 0; h < 2; h++) {
            const int li = lane + 32 * h;     // local term index
            const int t = t0 + li;
            if (li < TC && t < NI) {
                float di = fmaxf(delta_sm[li + 1] - delta_sm[li], 0.0f);
                const float m = reasoning_mask[b * LL + t + 2];
                int dist = rtp_b - t - 2;
                if (dist < 0) dist = 0;
                const float w = (dist < 5) ? (2.0f + (float)(5 - dist) * 0.5f) : 1.0f;
                ws += di * m * w;
                ms += m;
            }
        }
        #pragma unroll
        for (int o = 16; o > 0; o >>= 1) {
            ws += __shfl_xor_sync(0xffffffffu, ws, o);
            ms += __shfl_xor_sync(0xffffffffu, ms, o);
        }
        if (lane == 0) {
            atomicAdd(&g_ws, ws);
            atomicAdd(&g_ms, ms);
            __threadfence();
            const unsigned int my = atomicAdd(&g_ticket, 1u);
            if (my == nblocks - 1u) {
                __threadfence();
                const float tws = *(volatile float*)&g_ws;
                const float tms = *(volatile float*)&g_ms;
                out[0] = tws / (tms + 1e-9f);
                // reset for next graph replay (all blocks done: safe)
                g_ws = 0.0f;
                g_ms = 0.0f;
                g_ticket = 0u;
            }
        }
    }
}

extern "C" void kernel_launch(void* const* d_in, const int* in_sizes, int n_in,
                              void* d_out, int out_size) {
    const float* states = (const float*)d_in[0];
    const float* rmask  = (const float*)d_in[1];
    const int*   rtp    = (const int*)d_in[2];
    float*       out    = (float*)d_out;

    dim3 grid(XBLK, BB);   // (74, 8) = 592 blocks = 148 SMs x 4
    fused_kernel<<<grid, 256>>>(states, rmask, rtp, out);
}